// round 2
// baseline (speedup 1.0000x reference)
#include <cuda_runtime.h>
#include <math.h>

#define BB 4
#define TT 336
#define NN 862
#define DD 64
#define RR 8
#define KK 6
#define PP 96
#define NBMAX 8

// ---------------- device scratch ----------------
__device__ float g_xbar[BB*NN];
__device__ float g_xT[BB*NN*TT];
__device__ float g_y[BB*NN*TT];
__device__ float g_ya[BB*NN*TT];
__device__ float g_P[BB*(NN+1)*TT];
__device__ float g_xsorted[BB*NN];
__device__ int   g_sid[BB*NN];
__device__ float g_U1[TT*PP];
__device__ float g_U2[TT*PP];
__device__ float g_Sdp[DD*PP];
__device__ float g_constP[PP];
__device__ float g_cwP[PP];
__device__ float g_sgate[1];
__device__ double g_A, g_G, g_A2, g_G2;
__device__ float g_c0[DD];
__device__ float g_v[DD];
__device__ float g_w[DD];
__device__ float g_dinv[NN];
__device__ float g_rA[NN];
__device__ int   g_csr_cnt[NN];
__device__ int   g_csr_col[NN*NN];
__device__ float g_csr_val[NN*NN];
// per (b,n) selection: buckets over sorted order
__device__ int   g_nb[BB*NN];
__device__ float g_invden[BB*NN];
__device__ float g_bval[BB*NN*NBMAX];
__device__ int   g_blo[BB*NN*NBMAX];
__device__ int   g_bhi[BB*NN*NBMAX];

__device__ __forceinline__ float warp_sum(float v) {
    for (int o = 16; o; o >>= 1) v += __shfl_down_sync(0xffffffffu, v, o);
    return v;
}

// fp32-correctly-rounded exp for our regime; matches fl32(exp(d)) to <1e-13 rel
__device__ __forceinline__ float exp_f32cr(float d) {
    double x = (double)d;
    if (d > -0.001f && d <= 0.001f) {
        // cubic Taylor in double: error < 4e-14, far below fp32 ulp
        return (float)(1.0 + x*(1.0 + x*(0.5 + x*(1.0/6.0))));
    }
    return (float)exp(x);
}

// ---------------- kernels ----------------

// derived scalars (double where it matters for logits coefficients)
__global__ void k_scalars(const float* We, const float* be, const float* W1,
                          const float* W2, const float* gate, const float* Wg) {
    int tid = threadIdx.x; // 64
    __shared__ double a1[RR], b1[RR], a2[RR], b2[RR];
    float s = 1.f / (1.f + expf(-gate[0]));
    if (tid < RR) {
        double s1 = 0, s2 = 0, s3 = 0, s4 = 0;
        for (int d = 0; d < DD; d++) {
            double w1 = W1[d*RR + tid], w2 = W2[d*RR + tid];
            double we = We[d], beq = be[d];
            s1 += we*w1; s2 += beq*w1; s3 += we*w2; s4 += beq*w2;
        }
        a1[tid] = s1; b1[tid] = s2; a2[tid] = s3; b2[tid] = s4;
    }
    if (tid < DD) {
        float vv = 0, ww = 0;
        for (int d = 0; d < DD; d++) {
            float wg = Wg[d*DD + tid];
            vv += We[d]*wg;
            ww += (1.f + s)*be[d]*wg;
        }
        g_v[tid] = vv; g_w[tid] = ww; g_c0[tid] = (1.f + s)*be[tid];
    }
    __syncthreads();
    if (tid == 0) {
        double A = 0, G = 0, A2 = 0, G2 = 0;
        for (int r = 0; r < RR; r++) {
            A += a1[r]*a2[r]; G += b1[r]*a2[r];
            A2 += a1[r]*b2[r]; G2 += b1[r]*b2[r];
        }
        double inv = 1.0 / sqrt(8.0);
        g_A = A*inv; g_G = G*inv; g_A2 = A2*inv; g_G2 = G2*inv;
        g_sgate[0] = s;
    }
}

__global__ void k_xbar(const float* __restrict__ x) {
    int idx = blockIdx.x*blockDim.x + threadIdx.x;
    if (idx >= BB*NN) return;
    int b = idx / NN, n = idx % NN;
    float s = 0;
    for (int t = 0; t < TT; t++) s += x[(b*TT + t)*NN + n];
    g_xbar[idx] = s * (1.f / TT);
}

__global__ void k_transpose(const float* __restrict__ x) {
    __shared__ float tile[32][33];
    int b = blockIdx.z;
    int n = blockIdx.x*32 + threadIdx.x;
    int t = blockIdx.y*32 + threadIdx.y;
    if (n < NN && t < TT) tile[threadIdx.y][threadIdx.x] = x[(b*TT + t)*NN + n];
    __syncthreads();
    int n2 = blockIdx.x*32 + threadIdx.y;
    int t2 = blockIdx.y*32 + threadIdx.x;
    if (n2 < NN && t2 < TT) g_xT[(b*NN + n2)*TT + t2] = tile[threadIdx.x][threadIdx.y];
}

// stable descending sort of xbar per batch (rank sort, O(N^2) but tiny)
__global__ void k_sort() {
    int b = blockIdx.x, tid = threadIdx.x; // 256
    __shared__ float sx[NN];
    for (int m = tid; m < NN; m += 256) sx[m] = g_xbar[b*NN + m];
    __syncthreads();
    for (int m = tid; m < NN; m += 256) {
        float v = sx[m];
        int r = 0;
        for (int j = 0; j < NN; j++) {
            float u = sx[j];
            r += (u > v) || (u == v && j < m);
        }
        g_sid[b*NN + r] = m;
        g_xsorted[b*NN + r] = v;
    }
}

// prefix sums of xT rows in sorted order: P[b][j][t] = sum_{i<j} xT[b, sid[i], t]
__global__ void k_prefix() {
    int b = blockIdx.x;
    int t = blockIdx.y*128 + threadIdx.x;
    if (t >= TT) return;
    float* P = &g_P[b*(NN+1)*TT];
    const int* sid = &g_sid[b*NN];
    float acc = 0;
    P[t] = 0;
    for (int j = 0; j < NN; j++) {
        acc += g_xT[(b*NN + sid[j])*TT + t];
        P[(j+1)*TT + t] = acc;
    }
}

// faithful fp32 softmax + top-K(ties) selection per (b,n). One warp per row.
__global__ void k_sel() {
    int gw = blockIdx.x*4 + (threadIdx.x >> 5);
    if (gw >= BB*NN) return;
    int lane = threadIdx.x & 31;
    int b = gw / NN;
    const unsigned FULL = 0xffffffffu;

    double xn = (double)g_xbar[gw];
    double p = g_A*xn + g_G;
    double q = g_A2*xn + g_G2;
    const float* xv = &g_xbar[b*NN];

    // pass 1: fp32 row max of l
    float lmax = -3.4e38f;
    for (int m = lane; m < NN; m += 32) {
        float l = (float)(p*(double)xv[m] + q);
        lmax = fmaxf(lmax, l);
    }
    for (int o = 16; o; o >>= 1) lmax = fmaxf(lmax, __shfl_xor_sync(FULL, lmax, o));

    // pass 2: Z = fl32 of exact sum of fp32 e's
    double zd = 0;
    for (int m = lane; m < NN; m += 32) {
        float l = (float)(p*(double)xv[m] + q);
        float e = exp_f32cr(l - lmax);
        zd += (double)e;
    }
    for (int o = 16; o; o >>= 1) zd += __shfl_xor_sync(FULL, zd, o);
    float Zf = (float)zd;

    int dir = (p < 0.0);  // traversal j -> sorted index (dir: from tail)
    const float* xs = &g_xsorted[b*NN];

    // threshold = adj at traversal position KK-1 (6th largest adj)
    float thresh;
    {
        int sj = dir ? (NN-1-(KK-1)) : (KK-1);
        float l = (float)(p*(double)xs[sj] + q);
        thresh = __fdiv_rn(exp_f32cr(l - lmax), Zf);
    }

    // scan the traversal prefix: J = selected count, bucket boundaries by adj value
    int nb = 0, J = NN;
    float bval[NBMAX];
    int bs[NBMAX];
    int stop = 0;
    for (int base = 0; base < NN && !stop; base += 32) {
        int j = base + lane;
        float adj = 0; int sel = 0;
        if (j < NN) {
            int sj = dir ? (NN-1-j) : j;
            float l = (float)(p*(double)xs[sj] + q);
            adj = __fdiv_rn(exp_f32cr(l - lmax), Zf);
            sel = (adj >= thresh);
        }
        unsigned bal = __ballot_sync(FULL, sel);
        for (int k = 0; k < 32; k++) {
            float av = __shfl_sync(FULL, adj, k);
            if (lane == 0 && !stop) {
                int jj = base + k;
                int s2 = (jj < NN) && ((bal >> k) & 1u);
                if (!s2) { J = jj; stop = 1; }
                else if (nb == 0 || av != bval[nb-1]) {
                    if (nb < NBMAX) { bval[nb] = av; bs[nb] = jj; nb++; }
                }
            }
        }
        stop = __shfl_sync(FULL, stop, 0);
    }

    if (lane == 0) {
        double den = 0;
        for (int i = 0; i < nb; i++) {
            int hi = (i+1 < nb) ? bs[i+1] : J;
            den += (double)bval[i] * (double)(hi - bs[i]);
        }
        if (den < 1e-12) den = 1e-12;
        g_nb[gw] = nb;
        g_invden[gw] = (float)(1.0/den);
        for (int i = 0; i < nb; i++) {
            int lo_t = bs[i];
            int hi_t = (i+1 < nb) ? bs[i+1] : J;
            int lo_s = dir ? (NN - hi_t) : lo_t;
            int hi_s = dir ? (NN - lo_t) : hi_t;
            g_bval[gw*NBMAX + i] = bval[i];
            g_blo[gw*NBMAX + i] = lo_s;
            g_bhi[gw*NBMAX + i] = hi_s;
        }
    }
}

__global__ void k_deg(const float* __restrict__ A) {
    int w = (blockIdx.x*blockDim.x + threadIdx.x) >> 5;
    int lane = threadIdx.x & 31;
    if (w >= NN) return;
    float s = 0;
    for (int m = lane; m < NN; m += 32) s += A[w*NN + m];
    s = warp_sum(s);
    if (lane == 0) g_dinv[w] = (s > 0.f) ? (1.f / sqrtf(s)) : 0.f;
}

__global__ void k_csr(const float* __restrict__ A) {
    int w = (blockIdx.x*blockDim.x + threadIdx.x) >> 5;
    int lane = threadIdx.x & 31;
    if (w >= NN) return;
    int n = w;
    float dn = g_dinv[n];
    int base = 0; float rsum = 0;
    for (int m0 = 0; m0 < NN; m0 += 32) {
        int m = m0 + lane;
        float v = 0;
        if (m < NN) v = A[n*NN + m] * dn * g_dinv[m];
        unsigned mask = __ballot_sync(0xffffffffu, v != 0.f);
        if (v != 0.f) {
            int pos = base + __popc(mask & ((1u << lane) - 1u));
            g_csr_col[n*NN + pos] = m;
            g_csr_val[n*NN + pos] = v;
        }
        base += __popc(mask);
        float cs = warp_sum(v);
        if (lane == 0) rsum += cs;
    }
    if (lane == 0) { g_csr_cnt[n] = base; g_rA[n] = rsum; }
}

// y[b,n,t] = xT + s * (sum_buckets val*(P[hi]-P[lo])) * invden
__global__ void k_y() {
    int id = blockIdx.x;
    int b = id / NN;
    int tid = threadIdx.x; // 128
    __shared__ float sval[NBMAX]; __shared__ int slo[NBMAX], shi[NBMAX];
    __shared__ int snb; __shared__ float sinv;
    if (tid == 0) { snb = g_nb[id]; sinv = g_invden[id]; }
    if (tid < NBMAX) {
        sval[tid] = g_bval[id*NBMAX + tid];
        slo[tid]  = g_blo[id*NBMAX + tid];
        shi[tid]  = g_bhi[id*NBMAX + tid];
    }
    __syncthreads();
    int nb = snb;
    float s = g_sgate[0] * sinv;
    const float* P = &g_P[b*(NN+1)*TT];
    const float* xrow = &g_xT[id*TT];
    float* yrow = &g_y[id*TT];
    for (int t = tid; t < TT; t += 128) {
        float mix = 0;
        for (int i = 0; i < nb; i++)
            mix += sval[i]*(P[shi[i]*TT + t] - P[slo[i]*TT + t]);
        yrow[t] = xrow[t] + s*mix;
    }
}

// ya[b,n,t] = A_hat csr row applied to y
__global__ void k_ya() {
    int id = blockIdx.x;
    int b = id / NN, n = id % NN;
    int tid = threadIdx.x; // 128
    __shared__ int   scol[128];
    __shared__ float sval[128];
    int cnt = g_csr_cnt[n];
    float a0 = 0, a1 = 0, a2 = 0;
    int t0 = tid, t1 = tid + 128, t2 = tid + 256;
    for (int kc = 0; kc < cnt; kc += 128) {
        int kend = min(128, cnt - kc);
        if (tid < kend) {
            scol[tid] = g_csr_col[n*NN + kc + tid];
            sval[tid] = g_csr_val[n*NN + kc + tid];
        }
        __syncthreads();
        for (int k = 0; k < kend; k++) {
            float v = sval[k];
            const float* yr = &g_y[(b*NN + scol[k])*TT];
            a0 += v * yr[t0];
            a1 += v * yr[t1];
            if (t2 < TT) a2 += v * yr[t2];
        }
        __syncthreads();
    }
    float* yar = &g_ya[id*TT];
    yar[t0] = a0;
    yar[t1] = a1;
    if (t2 < TT) yar[t2] = a2;
}

__global__ void k_U(const float* __restrict__ We, const float* __restrict__ Wh) {
    int t = blockIdx.x, p = threadIdx.x; // 96
    __shared__ float sWe[DD], sv[DD];
    if (p < DD) { sWe[p] = We[p]; sv[p] = g_v[p]; }
    __syncthreads();
    float u1 = 0, u2 = 0;
    const float* base = Wh + (size_t)t*DD*PP;
    for (int d = 0; d < DD; d++) {
        float w = base[d*PP + p];
        u1 += sWe[d]*w; u2 += sv[d]*w;
    }
    g_U1[t*PP + p] = u1; g_U2[t*PP + p] = u2;
}

__global__ void k_S(const float* __restrict__ Wh) {
    int d = blockIdx.x, p = threadIdx.x; // 96
    float s = 0;
    for (int t = 0; t < TT; t++) s += Wh[((size_t)t*DD + d)*PP + p];
    g_Sdp[d*PP + p] = s;
}

__global__ void k_cp(const float* __restrict__ bh) {
    int p = threadIdx.x; // 96, 1 block
    float c = 0, cw = 0;
    for (int d = 0; d < DD; d++) {
        float sdp = g_Sdp[d*PP + p];
        c += g_c0[d]*sdp; cw += g_w[d]*sdp;
    }
    g_constP[p] = c + bh[p];
    g_cwP[p] = cw;
}

// out[b,p,n] = sum_t y*U1 + g*sum_t ya*U2 + constP[p] + g*rA[n]*cwP[p]
__global__ void k_out(const float* __restrict__ ggp, float* __restrict__ out) {
    int p = threadIdx.x;               // 96
    int b = blockIdx.y;
    int n0 = blockIdx.x*8;
    int nrows = min(8, NN - n0);
    __shared__ float ys[8*TT];
    __shared__ float yas[8*TT];
    for (int idx = p; idx < nrows*TT; idx += PP) {
        int i = idx / TT, t = idx - i*TT;
        ys[idx]  = g_y[(b*NN + n0 + i)*TT + t];
        yas[idx] = g_ya[(b*NN + n0 + i)*TT + t];
    }
    __syncthreads();
    float gg = ggp[0];
    float acc[8] = {0,0,0,0,0,0,0,0};
    #pragma unroll 2
    for (int t = 0; t < TT; t++) {
        float u1 = g_U1[t*PP + p];
        float u2 = gg * g_U2[t*PP + p];
        #pragma unroll
        for (int i = 0; i < 8; i++)
            acc[i] += ys[i*TT + t]*u1 + yas[i*TT + t]*u2;
    }
    for (int i = 0; i < nrows; i++) {
        int n = n0 + i;
        out[((size_t)b*PP + p)*NN + n] = acc[i] + g_constP[p] + gg * g_rA[n] * g_cwP[p];
    }
}

// ---------------- launcher ----------------
extern "C" void kernel_launch(void* const* d_in, const int* in_sizes, int n_in,
                              void* d_out, int out_size) {
    const float* x    = (const float*)d_in[0];
    const float* We   = (const float*)d_in[1];
    const float* be   = (const float*)d_in[2];
    const float* W1   = (const float*)d_in[3];
    const float* W2   = (const float*)d_in[4];
    const float* gate = (const float*)d_in[5];
    const float* Apr  = (const float*)d_in[6];
    const float* Wg   = (const float*)d_in[7];
    const float* ggcn = (const float*)d_in[8];
    const float* Wh   = (const float*)d_in[9];
    const float* bh   = (const float*)d_in[10];
    float* out = (float*)d_out;

    k_scalars<<<1, 64>>>(We, be, W1, W2, gate, Wg);
    k_xbar<<<(BB*NN + 255)/256, 256>>>(x);
    {
        dim3 gt((NN + 31)/32, (TT + 31)/32, BB);
        k_transpose<<<gt, dim3(32, 32)>>>(x);
    }
    k_sort<<<BB, 256>>>();
    k_prefix<<<dim3(BB, (TT + 127)/128), 128>>>();
    k_sel<<<(BB*NN + 3)/4, 128>>>();
    k_deg<<<(NN*32 + 255)/256, 256>>>(Apr);
    k_csr<<<(NN*32 + 255)/256, 256>>>(Apr);
    k_y<<<BB*NN, 128>>>();
    k_ya<<<BB*NN, 128>>>();
    k_S<<<DD, PP>>>(Wh);
    k_U<<<TT, PP>>>(We, Wh);
    k_cp<<<1, PP>>>(bh);
    k_out<<<dim3((NN + 7)/8, BB), PP>>>(ggcn, out);
}

// round 5
// speedup vs baseline: 4.5863x; 4.5863x over previous
#include <cuda_runtime.h>
#include <math.h>

#define BB 4
#define TT 336
#define NN 862
#define DD 64
#define RR 8
#define KK 6
#define PP 96
#define NBMAX 8
#define CH 32
#define NCH 27      // ceil(862/32)
#define ROWS 12     // k_out row tile

// ---------------- device scratch ----------------
__device__ float g_xbar[BB*NN];
__device__ float g_xT[BB*NN*TT];
__device__ float g_y[BB*NN*TT];
__device__ float g_Pl[BB*NN*TT];          // chunk-local prefixes of sorted rows
__device__ float g_chtot[BB*NCH*TT];
__device__ float g_Off[BB*NCH*TT];
__device__ float g_xsorted[BB*NN];
__device__ int   g_sid[BB*NN];
__device__ float g_U1[TT*PP];
__device__ float g_U2[TT*PP];
__device__ float g_Sdp[DD*PP];
__device__ float g_constP[PP];
__device__ float g_cwP[PP];
__device__ float g_sgate[1];
__device__ double g_cA, g_cG, g_cA2, g_cG2;
__device__ float g_c0[DD];
__device__ float g_v[DD];
__device__ float g_w[DD];
__device__ float g_dinv[NN];
__device__ float g_rA[NN];
__device__ int   g_csr_cnt[NN];
__device__ int   g_csr_col[NN*NN];
__device__ float g_csr_val[NN*NN];
__device__ int   g_nb[BB*NN];
__device__ float g_invden[BB*NN];
__device__ float g_bval[BB*NN*NBMAX];
__device__ int   g_blo[BB*NN*NBMAX];
__device__ int   g_bhi[BB*NN*NBMAX];
__device__ float g_O1[BB*NN*PP];
__device__ float g_O2[BB*NN*PP];

__device__ __forceinline__ float warp_sum(float v) {
    for (int o = 16; o; o >>= 1) v += __shfl_down_sync(0xffffffffu, v, o);
    return v;
}

// fp32-correctly-rounded exp for our regime (identical to the passing R2 version)
__device__ __forceinline__ float exp_f32cr(float d) {
    double x = (double)d;
    if (d > -0.001f && d <= 0.001f) {
        return (float)(1.0 + x*(1.0 + x*(0.5 + x*(1.0/6.0))));
    }
    return (float)exp(x);
}

// ================= stage 1: transpose + xbar + deg + scalars + S =================
#define S1_TP   1188   // 27*11*4
#define S1_XB   (S1_TP + 14)
#define S1_DEG  (S1_XB + 108)
#define S1_SCAL (S1_DEG + 1)
#define S1_S    (S1_SCAL + 24)

__global__ void k_stage1(const float* __restrict__ x, const float* __restrict__ We,
                         const float* __restrict__ be, const float* __restrict__ W1,
                         const float* __restrict__ W2, const float* __restrict__ gate,
                         const float* __restrict__ Apr, const float* __restrict__ Wg,
                         const float* __restrict__ Wh) {
    __shared__ float sh[1088];
    int blk = blockIdx.x;
    int tid = threadIdx.x; // 256

    if (blk < S1_TP) {
        int bz = blk / (27*11);
        int rem = blk % (27*11);
        int tn = rem % 27, tt2 = rem / 27;
        int lx = tid & 31, ly = tid >> 5; // 8 rows
        #pragma unroll
        for (int r = 0; r < 32; r += 8) {
            int n = tn*32 + lx, t = tt2*32 + ly + r;
            if (n < NN && t < TT) sh[(ly+r)*33 + lx] = x[(bz*TT + t)*NN + n];
        }
        __syncthreads();
        #pragma unroll
        for (int r = 0; r < 32; r += 8) {
            int n2 = tn*32 + ly + r, t2 = tt2*32 + lx;
            if (n2 < NN && t2 < TT) g_xT[(bz*NN + n2)*TT + t2] = sh[lx*33 + (ly+r)];
        }
    } else if (blk < S1_XB) {
        int idx = (blk - S1_TP)*256 + tid;
        if (idx < BB*NN) {
            int b = idx / NN, n = idx % NN;
            float s = 0;
            for (int t = 0; t < TT; t++) s += x[(b*TT + t)*NN + n];
            g_xbar[idx] = s * (1.f / TT);
        }
    } else if (blk < S1_DEG) {
        int w = (blk - S1_XB)*8 + (tid >> 5);
        int lane = tid & 31;
        if (w < NN) {
            float s = 0;
            for (int m = lane; m < NN; m += 32) s += Apr[w*NN + m];
            s = warp_sum(s);
            if (lane == 0) g_dinv[w] = (s > 0.f) ? (1.f / sqrtf(s)) : 0.f;
        }
    } else if (blk < S1_SCAL) {
        double* da = (double*)sh;
        float s = 1.f / (1.f + expf(-gate[0]));
        if (tid < RR) {
            double s1 = 0, s2 = 0, s3 = 0, s4 = 0;
            for (int d = 0; d < DD; d++) {
                double w1 = W1[d*RR + tid], w2 = W2[d*RR + tid];
                double we = We[d], beq = be[d];
                s1 += we*w1; s2 += beq*w1; s3 += we*w2; s4 += beq*w2;
            }
            da[tid] = s1; da[8+tid] = s2; da[16+tid] = s3; da[24+tid] = s4;
        }
        if (tid < DD) {
            float vv = 0, ww = 0;
            for (int d = 0; d < DD; d++) {
                float wg = Wg[d*DD + tid];
                vv += We[d]*wg;
                ww += (1.f + s)*be[d]*wg;
            }
            g_v[tid] = vv; g_w[tid] = ww; g_c0[tid] = (1.f + s)*be[tid];
        }
        __syncthreads();
        if (tid == 0) {
            double A = 0, G = 0, A2 = 0, G2 = 0;
            for (int r = 0; r < RR; r++) {
                A += da[r]*da[16+r]; G += da[8+r]*da[16+r];
                A2 += da[r]*da[24+r]; G2 += da[8+r]*da[24+r];
            }
            double inv = 1.0 / sqrt(8.0);
            g_cA = A*inv; g_cG = G*inv; g_cA2 = A2*inv; g_cG2 = G2*inv;
            g_sgate[0] = s;
        }
    } else {
        int idx = (blk - S1_SCAL)*256 + tid;
        if (idx < DD*PP) {
            int d = idx / PP, p = idx % PP;
            float s = 0;
            for (int t = 0; t < TT; t++) s += Wh[((size_t)t*DD + d)*PP + p];
            g_Sdp[idx] = s;
        }
    }
}

// ================= stage 2: sort + csr + U + cp =================
#define S2_SORT 16
#define S2_CSR  (S2_SORT + 108)
#define S2_U    (S2_CSR + 126)
#define S2_CP   (S2_U + 1)

__global__ void k_stage2(const float* __restrict__ Apr, const float* __restrict__ We,
                         const float* __restrict__ Wh, const float* __restrict__ bh) {
    __shared__ float sh[1088];
    int blk = blockIdx.x;
    int tid = threadIdx.x; // 256

    if (blk < S2_SORT) {
        int b = blk >> 2, sub = blk & 3;
        for (int m = tid; m < NN; m += 256) sh[m] = g_xbar[b*NN + m];
        __syncthreads();
        int m = sub*256 + tid;
        if (m < NN) {
            float v = sh[m];
            int r = 0;
            for (int j = 0; j < NN; j++) {
                float u = sh[j];
                r += (u > v) || (u == v && j < m);
            }
            g_sid[b*NN + r] = m;
            g_xsorted[b*NN + r] = v;
        }
    } else if (blk < S2_CSR) {
        int n = (blk - S2_SORT)*8 + (tid >> 5);
        int lane = tid & 31;
        if (n < NN) {
            float dn = g_dinv[n];
            int base = 0; float rsum = 0;
            for (int m0 = 0; m0 < NN; m0 += 32) {
                int m = m0 + lane;
                float v = 0;
                if (m < NN) v = Apr[n*NN + m] * dn * g_dinv[m];
                unsigned mask = __ballot_sync(0xffffffffu, v != 0.f);
                if (v != 0.f) {
                    int pos = base + __popc(mask & ((1u << lane) - 1u));
                    g_csr_col[n*NN + pos] = m;
                    g_csr_val[n*NN + pos] = v;
                }
                base += __popc(mask);
                float cs = warp_sum(v);
                if (lane == 0) rsum += cs;
            }
            if (lane == 0) { g_csr_cnt[n] = base; g_rA[n] = rsum; }
        }
    } else if (blk < S2_U) {
        int idx = (blk - S2_CSR)*256 + tid;
        if (idx < TT*PP) {
            int t = idx / PP, p = idx % PP;
            float u1 = 0, u2 = 0;
            const float* basep = Wh + (size_t)t*DD*PP;
            for (int d = 0; d < DD; d++) {
                float w = basep[d*PP + p];
                u1 += We[d]*w; u2 += g_v[d]*w;
            }
            g_U1[idx] = u1; g_U2[idx] = u2;
        }
    } else {
        int p = tid;
        if (p < PP) {
            float c = 0, cw = 0;
            for (int d = 0; d < DD; d++) {
                float sdp = g_Sdp[d*PP + p];
                c += g_c0[d]*sdp; cw += g_w[d]*sdp;
            }
            g_constP[p] = c + bh[p];
            g_cwP[p] = cw;
        }
    }
}

// ================= stage 3: prefix phase1 + selection =================
#define S3_PFX 216
#define S3_SEL (S3_PFX + 16)

__global__ void k_stage3() {
    __shared__ float sh[1088];
    int blk = blockIdx.x;
    int tid = threadIdx.x; // 256

    if (blk < S3_PFX) {
        int b = blk / 54;
        int rem = blk % 54;
        int ch = rem >> 1, tt2 = rem & 1;
        int t = tt2*256 + tid;
        if (t < TT) {
            int j0 = ch*CH, j1 = min(j0 + CH, NN);
            const int* sid = &g_sid[b*NN];
            float acc = 0;
            for (int j = j0; j < j1; j++) {
                acc += g_xT[(b*NN + sid[j])*TT + t];
                g_Pl[(b*NN + j)*TT + t] = acc;
            }
            g_chtot[(b*NCH + ch)*TT + t] = acc;
        }
        return;
    }

    // ---- selection: one thread per (b,n) row ----
    int sblk = blk - S3_PFX;
    int b = sblk >> 2, sub = sblk & 3;
    for (int m = tid; m < NN; m += 256) sh[m] = g_xsorted[b*NN + m];
    __syncthreads();
    int n = sub*256 + tid;
    if (n >= NN) return;
    int gw = b*NN + n;

    double xn = (double)g_xbar[gw];
    double p = g_cA*xn + g_cG;
    double q = g_cA2*xn + g_cG2;
    int dir = (p < 0.0);

    auto EV = [&](int j) -> float {
        int sj = dir ? (NN-1-j) : j;
        return (float)(p*(double)sh[sj] + q);
    };

    float l0 = EV(0), lN = EV(NN-1);
    float lmax = fmaxf(l0, lN);

    // bucket walk along traversal order (E non-increasing)
    float be_[16]; int bst[16];
    int nbk = 0, pos = 0, stored_end = 0, nwalk = 0;
    double Zd = 0.0;
    bool fb = false;
    while (pos < NN) {
        float v = exp_f32cr(EV(pos) - lmax);
        int lo = pos, hi = NN - 1;
        while (lo < hi) {
            int mid = (lo + hi + 1) >> 1;
            if (exp_f32cr(EV(mid) - lmax) == v) lo = mid; else hi = mid - 1;
        }
        int end = lo + 1;
        Zd += (double)v * (double)(end - pos);
        if (nbk < 16) { be_[nbk] = v; bst[nbk] = pos; nbk++; stored_end = end; }
        pos = end;
        if (++nwalk > 96) { if (pos < NN) fb = true; break; }
    }

    float tval[NBMAX]; int tlo[NBMAX];
    int nb = 0, J = NN;

    if (!fb) {
        float Zf = (float)Zd;
        int ti = 0;
        while (ti + 1 < nbk && bst[ti+1] <= KK-1) ti++;
        float thresh = __fdiv_rn(be_[ti], Zf);
        bool done = false;
        for (int k = 0; k < nbk && !done; k++) {
            float adj = __fdiv_rn(be_[k], Zf);
            if (adj >= thresh) {
                if (nb == 0 || adj != tval[nb-1]) {
                    if (nb < NBMAX) { tval[nb] = adj; tlo[nb] = bst[k]; nb++; }
                }
            } else { J = bst[k]; done = true; }
        }
        if (!done) {
            if (nbk == 16 && stored_end < NN) fb = true;
            else J = NN;
        }
    }

    if (fb) {
        double Zd2 = 0;
        for (int j = 0; j < NN; j++) Zd2 += (double)exp_f32cr(EV(j) - lmax);
        float Zf2 = (float)Zd2;
        float thresh = __fdiv_rn(exp_f32cr(EV(KK-1) - lmax), Zf2);
        nb = 0; J = NN;
        for (int j = 0; j < NN; j++) {
            float adj = __fdiv_rn(exp_f32cr(EV(j) - lmax), Zf2);
            if (!(adj >= thresh)) { J = j; break; }
            if (nb == 0 || adj != tval[nb-1]) {
                if (nb < NBMAX) { tval[nb] = adj; tlo[nb] = j; nb++; }
            }
        }
    }

    double den = 0;
    for (int i = 0; i < nb; i++) {
        int hi = (i+1 < nb) ? tlo[i+1] : J;
        den += (double)tval[i] * (double)(hi - tlo[i]);
    }
    if (den < 1e-12) den = 1e-12;
    g_nb[gw] = nb;
    g_invden[gw] = (float)(1.0/den);
    for (int i = 0; i < nb && i < NBMAX; i++) {
        int lo_t = tlo[i];
        int hi_t = (i+1 < nb) ? tlo[i+1] : J;
        int lo_s = dir ? (NN - hi_t) : lo_t;
        int hi_s = dir ? (NN - lo_t) : hi_t;
        g_bval[gw*NBMAX + i] = tval[i];
        g_blo[gw*NBMAX + i] = lo_s;
        g_bhi[gw*NBMAX + i] = hi_s;
    }
}

// ================= stage 4: chunk offsets =================
__global__ void k_off() {
    int b = blockIdx.x;
    int t = blockIdx.y*256 + threadIdx.x;
    if (t >= TT) return;
    float off = 0;
    for (int c = 0; c < NCH; c++) {
        g_Off[(b*NCH + c)*TT + t] = off;
        off += g_chtot[(b*NCH + c)*TT + t];
    }
}

// ================= k_y: y = xT + s * bucket-weighted range sums =================
__global__ void k_y() {
    int id = blockIdx.x;
    int b = id / NN;
    int tid = threadIdx.x; // 128
    __shared__ float sval[NBMAX]; __shared__ int slo[NBMAX], shi[NBMAX];
    __shared__ int snb; __shared__ float sinv;
    if (tid == 0) { snb = g_nb[id]; sinv = g_invden[id]; }
    if (tid < NBMAX) {
        sval[tid] = g_bval[id*NBMAX + tid];
        slo[tid]  = g_blo[id*NBMAX + tid];
        shi[tid]  = g_bhi[id*NBMAX + tid];
    }
    __syncthreads();
    int nb = snb;
    if (nb > NBMAX) nb = NBMAX;
    float s = g_sgate[0] * sinv;
    const float* xrow = &g_xT[id*TT];
    float* yrow = &g_y[id*TT];
    const float* Pb = &g_Pl[b*NN*TT];
    const float* Ob = &g_Off[b*NCH*TT];
    for (int t = tid; t < TT; t += 128) {
        float mix = 0;
        for (int i = 0; i < nb; i++) {
            int hi = shi[i], lo = slo[i];
            float ph = (hi == 0) ? 0.f : (Pb[(hi-1)*TT + t] + Ob[((hi-1) >> 5)*TT + t]);
            float pl = (lo == 0) ? 0.f : (Pb[(lo-1)*TT + t] + Ob[((lo-1) >> 5)*TT + t]);
            mix += sval[i]*(ph - pl);
        }
        yrow[t] = xrow[t] + s*mix;
    }
}

// ================= k_out: O1 = Y@U1, O2 = Y@U2 =================
__global__ void k_out() {
    int p = threadIdx.x;  // 96
    int b = blockIdx.y;
    int n0 = blockIdx.x*ROWS;
    int nrows = min(ROWS, NN - n0);
    __shared__ __align__(16) float ys[TT*ROWS + 4];
    if (nrows < ROWS) {
        for (int idx = p; idx < TT*ROWS; idx += PP) ys[idx] = 0.f;
        __syncthreads();
    }
    for (int idx = p; idx < nrows*TT; idx += PP) {
        int i = idx / TT, t = idx - i*TT;
        ys[t*ROWS + i] = g_y[(b*NN + n0 + i)*TT + t];
    }
    __syncthreads();
    float acc1[ROWS], acc2[ROWS];
    #pragma unroll
    for (int i = 0; i < ROWS; i++) { acc1[i] = 0.f; acc2[i] = 0.f; }
    #pragma unroll 2
    for (int t = 0; t < TT; t++) {
        float u1 = g_U1[t*PP + p];
        float u2 = g_U2[t*PP + p];
        const float4* row = (const float4*)&ys[t*ROWS];
        float4 v0 = row[0], v1 = row[1], v2 = row[2];
        acc1[0] += v0.x*u1;  acc2[0] += v0.x*u2;
        acc1[1] += v0.y*u1;  acc2[1] += v0.y*u2;
        acc1[2] += v0.z*u1;  acc2[2] += v0.z*u2;
        acc1[3] += v0.w*u1;  acc2[3] += v0.w*u2;
        acc1[4] += v1.x*u1;  acc2[4] += v1.x*u2;
        acc1[5] += v1.y*u1;  acc2[5] += v1.y*u2;
        acc1[6] += v1.z*u1;  acc2[6] += v1.z*u2;
        acc1[7] += v1.w*u1;  acc2[7] += v1.w*u2;
        acc1[8] += v2.x*u1;  acc2[8] += v2.x*u2;
        acc1[9] += v2.y*u1;  acc2[9] += v2.y*u2;
        acc1[10] += v2.z*u1; acc2[10] += v2.z*u2;
        acc1[11] += v2.w*u1; acc2[11] += v2.w*u2;
    }
    for (int i = 0; i < nrows; i++) {
        int n = n0 + i;
        g_O1[(b*NN + n)*PP + p] = acc1[i];
        g_O2[(b*NN + n)*PP + p] = acc2[i];
    }
}

// ================= k_fin: out = O1 + g*A_hat@O2 + consts =================
__global__ void k_fin(const float* __restrict__ ggp, float* __restrict__ out) {
    int b = blockIdx.y;
    int n = blockIdx.x*32 + threadIdx.x;
    if (n >= NN) return;
    float gg = ggp[0];
    int cnt = g_csr_cnt[n];
    float rterm = gg * g_rA[n];
    for (int p = threadIdx.y; p < PP; p += 8) {
        float acc = 0;
        for (int k = 0; k < cnt; k++)
            acc += g_csr_val[n*NN + k] * g_O2[(b*NN + g_csr_col[n*NN + k])*PP + p];
        out[((size_t)b*PP + p)*NN + n] =
            g_O1[(b*NN + n)*PP + p] + gg*acc + g_constP[p] + rterm*g_cwP[p];
    }
}

// ---------------- launcher ----------------
extern "C" void kernel_launch(void* const* d_in, const int* in_sizes, int n_in,
                              void* d_out, int out_size) {
    const float* x    = (const float*)d_in[0];
    const float* We   = (const float*)d_in[1];
    const float* be   = (const float*)d_in[2];
    const float* W1   = (const float*)d_in[3];
    const float* W2   = (const float*)d_in[4];
    const float* gate = (const float*)d_in[5];
    const float* Apr  = (const float*)d_in[6];
    const float* Wg   = (const float*)d_in[7];
    const float* ggcn = (const float*)d_in[8];
    const float* Wh   = (const float*)d_in[9];
    const float* bh   = (const float*)d_in[10];
    float* out = (float*)d_out;

    k_stage1<<<S1_S, 256>>>(x, We, be, W1, W2, gate, Apr, Wg, Wh);
    k_stage2<<<S2_CP, 256>>>(Apr, We, Wh, bh);
    k_stage3<<<S3_SEL, 256>>>();
    k_off<<<dim3(BB, 2), 256>>>();
    k_y<<<BB*NN, 128>>>();
    k_out<<<dim3((NN + ROWS - 1)/ROWS, BB), PP>>>();
    k_fin<<<dim3((NN + 31)/32, BB), dim3(32, 8)>>>(ggcn, out);
}

// round 6
// speedup vs baseline: 4.5953x; 1.0020x over previous
#include <cuda_runtime.h>
#include <math.h>

#define BB 4
#define TT 336
#define NN 862
#define DD 64
#define RR 8
#define KK 6
#define PP 96
#define NBMAX 8
#define CH 32
#define NCH 27      // ceil(862/32)
#define ROWS 12     // k_out row tile

// ---------------- device scratch ----------------
__device__ float g_xbar[BB*NN];
__device__ float g_xT[BB*NN*TT];
__device__ float g_Pl[BB*NN*TT];          // chunk-local prefixes of sorted rows
__device__ float g_chtot[BB*NCH*TT];
__device__ float g_Off[BB*NCH*TT];
__device__ float g_xsorted[BB*NN];
__device__ int   g_sid[BB*NN];
__device__ float g_U1[TT*PP];
__device__ float g_U2[TT*PP];
__device__ float g_Sdp[DD*PP];
__device__ float g_constP[PP];
__device__ float g_cwP[PP];
__device__ float g_sgate[1];
__device__ double g_cA, g_cG, g_cA2, g_cG2;
__device__ float g_c0[DD];
__device__ float g_v[DD];
__device__ float g_w[DD];
__device__ float g_dinv[NN];
__device__ float g_rA[NN];
__device__ int   g_csr_cnt[NN];
__device__ int   g_csr_col[NN*NN];
__device__ float g_csr_val[NN*NN];
__device__ int   g_nb[BB*NN];
__device__ float g_invden[BB*NN];
__device__ float g_bval[BB*NN*NBMAX];
__device__ int   g_blo[BB*NN*NBMAX];
__device__ int   g_bhi[BB*NN*NBMAX];
__device__ float g_O1[BB*NN*PP];
__device__ float g_O2[BB*NN*PP];

__device__ __forceinline__ float warp_sum(float v) {
    for (int o = 16; o; o >>= 1) v += __shfl_down_sync(0xffffffffu, v, o);
    return v;
}

// fp32-correctly-rounded exp for our regime (identical to the passing R2/R5 version)
__device__ __forceinline__ float exp_f32cr(float d) {
    double x = (double)d;
    if (d > -0.001f && d <= 0.001f) {
        return (float)(1.0 + x*(1.0 + x*(0.5 + x*(1.0/6.0))));
    }
    return (float)exp(x);
}

// ================= stage 1: transpose + xbar + deg + scalars + S =================
#define S1_TP   1188   // 27*11*4
#define S1_XB   (S1_TP + 14)
#define S1_DEG  (S1_XB + 108)
#define S1_SCAL (S1_DEG + 1)
#define S1_S    (S1_SCAL + 24)

__global__ void k_stage1(const float* __restrict__ x, const float* __restrict__ We,
                         const float* __restrict__ be, const float* __restrict__ W1,
                         const float* __restrict__ W2, const float* __restrict__ gate,
                         const float* __restrict__ Apr, const float* __restrict__ Wg,
                         const float* __restrict__ Wh) {
    __shared__ float sh[1088];
    int blk = blockIdx.x;
    int tid = threadIdx.x; // 256

    if (blk < S1_TP) {
        int bz = blk / (27*11);
        int rem = blk % (27*11);
        int tn = rem % 27, tt2 = rem / 27;
        int lx = tid & 31, ly = tid >> 5; // 8 rows
        #pragma unroll
        for (int r = 0; r < 32; r += 8) {
            int n = tn*32 + lx, t = tt2*32 + ly + r;
            if (n < NN && t < TT) sh[(ly+r)*33 + lx] = x[(bz*TT + t)*NN + n];
        }
        __syncthreads();
        #pragma unroll
        for (int r = 0; r < 32; r += 8) {
            int n2 = tn*32 + ly + r, t2 = tt2*32 + lx;
            if (n2 < NN && t2 < TT) g_xT[(bz*NN + n2)*TT + t2] = sh[lx*33 + (ly+r)];
        }
    } else if (blk < S1_XB) {
        int idx = (blk - S1_TP)*256 + tid;
        if (idx < BB*NN) {
            int b = idx / NN, n = idx % NN;
            float s = 0;
            for (int t = 0; t < TT; t++) s += x[(b*TT + t)*NN + n];
            g_xbar[idx] = s * (1.f / TT);
        }
    } else if (blk < S1_DEG) {
        int w = (blk - S1_XB)*8 + (tid >> 5);
        int lane = tid & 31;
        if (w < NN) {
            float s = 0;
            for (int m = lane; m < NN; m += 32) s += Apr[w*NN + m];
            s = warp_sum(s);
            if (lane == 0) g_dinv[w] = (s > 0.f) ? (1.f / sqrtf(s)) : 0.f;
        }
    } else if (blk < S1_SCAL) {
        double* da = (double*)sh;
        float s = 1.f / (1.f + expf(-gate[0]));
        if (tid < RR) {
            double s1 = 0, s2 = 0, s3 = 0, s4 = 0;
            for (int d = 0; d < DD; d++) {
                double w1 = W1[d*RR + tid], w2 = W2[d*RR + tid];
                double we = We[d], beq = be[d];
                s1 += we*w1; s2 += beq*w1; s3 += we*w2; s4 += beq*w2;
            }
            da[tid] = s1; da[8+tid] = s2; da[16+tid] = s3; da[24+tid] = s4;
        }
        if (tid < DD) {
            float vv = 0, ww = 0;
            for (int d = 0; d < DD; d++) {
                float wg = Wg[d*DD + tid];
                vv += We[d]*wg;
                ww += (1.f + s)*be[d]*wg;
            }
            g_v[tid] = vv; g_w[tid] = ww; g_c0[tid] = (1.f + s)*be[tid];
        }
        __syncthreads();
        if (tid == 0) {
            double A = 0, G = 0, A2 = 0, G2 = 0;
            for (int r = 0; r < RR; r++) {
                A += da[r]*da[16+r]; G += da[8+r]*da[16+r];
                A2 += da[r]*da[24+r]; G2 += da[8+r]*da[24+r];
            }
            double inv = 1.0 / sqrt(8.0);
            g_cA = A*inv; g_cG = G*inv; g_cA2 = A2*inv; g_cG2 = G2*inv;
            g_sgate[0] = s;
        }
    } else {
        int idx = (blk - S1_SCAL)*256 + tid;
        if (idx < DD*PP) {
            int d = idx / PP, p = idx % PP;
            float s = 0;
            for (int t = 0; t < TT; t++) s += Wh[((size_t)t*DD + d)*PP + p];
            g_Sdp[idx] = s;
        }
    }
}

// ================= stage 2: sort + csr + U + cp =================
#define S2_SORT 16
#define S2_CSR  (S2_SORT + 108)
#define S2_U    (S2_CSR + 126)
#define S2_CP   (S2_U + 1)

__global__ void k_stage2(const float* __restrict__ Apr, const float* __restrict__ We,
                         const float* __restrict__ Wh, const float* __restrict__ bh) {
    __shared__ float sh[1088];
    int blk = blockIdx.x;
    int tid = threadIdx.x; // 256

    if (blk < S2_SORT) {
        int b = blk >> 2, sub = blk & 3;
        for (int m = tid; m < NN; m += 256) sh[m] = g_xbar[b*NN + m];
        __syncthreads();
        int m = sub*256 + tid;
        if (m < NN) {
            float v = sh[m];
            int r = 0;
            for (int j = 0; j < NN; j++) {
                float u = sh[j];
                r += (u > v) || (u == v && j < m);
            }
            g_sid[b*NN + r] = m;
            g_xsorted[b*NN + r] = v;
        }
    } else if (blk < S2_CSR) {
        int n = (blk - S2_SORT)*8 + (tid >> 5);
        int lane = tid & 31;
        if (n < NN) {
            float dn = g_dinv[n];
            int base = 0; float rsum = 0;
            for (int m0 = 0; m0 < NN; m0 += 32) {
                int m = m0 + lane;
                float v = 0;
                if (m < NN) v = Apr[n*NN + m] * dn * g_dinv[m];
                unsigned mask = __ballot_sync(0xffffffffu, v != 0.f);
                if (v != 0.f) {
                    int pos = base + __popc(mask & ((1u << lane) - 1u));
                    g_csr_col[n*NN + pos] = m;
                    g_csr_val[n*NN + pos] = v;
                }
                base += __popc(mask);
                float cs = warp_sum(v);
                if (lane == 0) rsum += cs;
            }
            if (lane == 0) { g_csr_cnt[n] = base; g_rA[n] = rsum; }
        }
    } else if (blk < S2_U) {
        int idx = (blk - S2_CSR)*256 + tid;
        if (idx < TT*PP) {
            int t = idx / PP, p = idx % PP;
            float u1 = 0, u2 = 0;
            const float* basep = Wh + (size_t)t*DD*PP;
            for (int d = 0; d < DD; d++) {
                float w = basep[d*PP + p];
                u1 += We[d]*w; u2 += g_v[d]*w;
            }
            g_U1[idx] = u1; g_U2[idx] = u2;
        }
    } else {
        int p = tid;
        if (p < PP) {
            float c = 0, cw = 0;
            for (int d = 0; d < DD; d++) {
                float sdp = g_Sdp[d*PP + p];
                c += g_c0[d]*sdp; cw += g_w[d]*sdp;
            }
            g_constP[p] = c + bh[p];
            g_cwP[p] = cw;
        }
    }
}

// ================= stage 3: prefix phase1 + selection =================
#define S3_PFX 216
#define S3_SEL (S3_PFX + 16)

__global__ void k_stage3() {
    __shared__ float sh[1088];
    int blk = blockIdx.x;
    int tid = threadIdx.x; // 256

    if (blk < S3_PFX) {
        int b = blk / 54;
        int rem = blk % 54;
        int ch = rem >> 1, tt2 = rem & 1;
        int t = tt2*256 + tid;
        if (t < TT) {
            int j0 = ch*CH, j1 = min(j0 + CH, NN);
            const int* sid = &g_sid[b*NN];
            float acc = 0;
            for (int j = j0; j < j1; j++) {
                acc += g_xT[(b*NN + sid[j])*TT + t];
                g_Pl[(b*NN + j)*TT + t] = acc;
            }
            g_chtot[(b*NCH + ch)*TT + t] = acc;
        }
        return;
    }

    // ---- selection: one thread per (b,n) row ----
    int sblk = blk - S3_PFX;
    int b = sblk >> 2, sub = sblk & 3;
    for (int m = tid; m < NN; m += 256) sh[m] = g_xsorted[b*NN + m];
    __syncthreads();
    int n = sub*256 + tid;
    if (n >= NN) return;
    int gw = b*NN + n;

    double xn = (double)g_xbar[gw];
    double p = g_cA*xn + g_cG;
    double q = g_cA2*xn + g_cG2;
    int dir = (p < 0.0);

    auto EV = [&](int j) -> float {
        int sj = dir ? (NN-1-j) : j;
        return (float)(p*(double)sh[sj] + q);
    };

    float l0 = EV(0), lN = EV(NN-1);
    float lmax = fmaxf(l0, lN);

    // bucket walk along traversal order (E non-increasing)
    float be_[16]; int bst[16];
    int nbk = 0, pos = 0, stored_end = 0, nwalk = 0;
    double Zd = 0.0;
    bool fb = false;
    while (pos < NN) {
        float v = exp_f32cr(EV(pos) - lmax);
        int lo = pos, hi = NN - 1;
        while (lo < hi) {
            int mid = (lo + hi + 1) >> 1;
            if (exp_f32cr(EV(mid) - lmax) == v) lo = mid; else hi = mid - 1;
        }
        int end = lo + 1;
        Zd += (double)v * (double)(end - pos);
        if (nbk < 16) { be_[nbk] = v; bst[nbk] = pos; nbk++; stored_end = end; }
        pos = end;
        if (++nwalk > 96) { if (pos < NN) fb = true; break; }
    }

    float tval[NBMAX]; int tlo[NBMAX];
    int nb = 0, J = NN;

    if (!fb) {
        float Zf = (float)Zd;
        int ti = 0;
        while (ti + 1 < nbk && bst[ti+1] <= KK-1) ti++;
        float thresh = __fdiv_rn(be_[ti], Zf);
        bool done = false;
        for (int k = 0; k < nbk && !done; k++) {
            float adj = __fdiv_rn(be_[k], Zf);
            if (adj >= thresh) {
                if (nb == 0 || adj != tval[nb-1]) {
                    if (nb < NBMAX) { tval[nb] = adj; tlo[nb] = bst[k]; nb++; }
                }
            } else { J = bst[k]; done = true; }
        }
        if (!done) {
            if (nbk == 16 && stored_end < NN) fb = true;
            else J = NN;
        }
    }

    if (fb) {
        double Zd2 = 0;
        for (int j = 0; j < NN; j++) Zd2 += (double)exp_f32cr(EV(j) - lmax);
        float Zf2 = (float)Zd2;
        float thresh = __fdiv_rn(exp_f32cr(EV(KK-1) - lmax), Zf2);
        nb = 0; J = NN;
        for (int j = 0; j < NN; j++) {
            float adj = __fdiv_rn(exp_f32cr(EV(j) - lmax), Zf2);
            if (!(adj >= thresh)) { J = j; break; }
            if (nb == 0 || adj != tval[nb-1]) {
                if (nb < NBMAX) { tval[nb] = adj; tlo[nb] = j; nb++; }
            }
        }
    }

    double den = 0;
    for (int i = 0; i < nb; i++) {
        int hi = (i+1 < nb) ? tlo[i+1] : J;
        den += (double)tval[i] * (double)(hi - tlo[i]);
    }
    if (den < 1e-12) den = 1e-12;
    g_nb[gw] = nb;
    g_invden[gw] = (float)(1.0/den);
    for (int i = 0; i < nb && i < NBMAX; i++) {
        int lo_t = tlo[i];
        int hi_t = (i+1 < nb) ? tlo[i+1] : J;
        int lo_s = dir ? (NN - hi_t) : lo_t;
        int hi_s = dir ? (NN - lo_t) : hi_t;
        g_bval[gw*NBMAX + i] = tval[i];
        g_blo[gw*NBMAX + i] = lo_s;
        g_bhi[gw*NBMAX + i] = hi_s;
    }
}

// ================= k_off: chunk offsets (MLP-batched scan) =================
// one thread per (b,t): load all 27 chtot values independently, scan in regs
__global__ void k_off() {
    int b = blockIdx.y;
    int t = blockIdx.x*128 + threadIdx.x;
    if (t >= TT) return;
    float v[NCH];
    const float* src = &g_chtot[b*NCH*TT + t];
    #pragma unroll
    for (int c = 0; c < NCH; c++) v[c] = src[c*TT];   // independent loads (MLP)
    float off = 0;
    float* dst = &g_Off[b*NCH*TT + t];
    #pragma unroll
    for (int c = 0; c < NCH; c++) {
        dst[c*TT] = off;
        off += v[c];
    }
}

// ================= k_out: fused y-construction + O1 = Y@U1, O2 = Y@U2 =================
__global__ void k_out() {
    int p = threadIdx.x;  // 96
    int b = blockIdx.y;
    int n0 = blockIdx.x*ROWS;
    int nrows = min(ROWS, NN - n0);
    __shared__ __align__(16) float ys[TT*ROWS + 4];
    __shared__ float sbv[ROWS][NBMAX];
    __shared__ int   sblo[ROWS][NBMAX];
    __shared__ int   sbhi[ROWS][NBMAX];
    __shared__ float srow[ROWS];
    __shared__ int   snbr[ROWS];

    if (nrows < ROWS) {
        for (int idx = p; idx < TT*ROWS; idx += PP) ys[idx] = 0.f;
    }
    // bucket metadata for this block's rows
    if (p < nrows) {
        int id = b*NN + n0 + p;
        int nb = g_nb[id]; if (nb > NBMAX) nb = NBMAX;
        snbr[p] = nb;
        srow[p] = g_sgate[0] * g_invden[id];
        for (int j = 0; j < NBMAX; j++) {
            sbv[p][j]  = g_bval[id*NBMAX + j];
            sblo[p][j] = g_blo[id*NBMAX + j];
            sbhi[p][j] = g_bhi[id*NBMAX + j];
        }
    }
    __syncthreads();

    // build y rows in smem: y = xT + s * bucket-weighted range sums
    const float* Pb = &g_Pl[b*NN*TT];
    const float* Ob = &g_Off[b*NCH*TT];
    for (int idx = p; idx < nrows*TT; idx += PP) {
        int i = idx / TT, t = idx - i*TT;
        float mix = 0;
        int nb = snbr[i];
        for (int k2 = 0; k2 < nb; k2++) {
            int hi = sbhi[i][k2], lo = sblo[i][k2];
            float ph = (hi == 0) ? 0.f : (Pb[(hi-1)*TT + t] + Ob[((hi-1) >> 5)*TT + t]);
            float pl = (lo == 0) ? 0.f : (Pb[(lo-1)*TT + t] + Ob[((lo-1) >> 5)*TT + t]);
            mix += sbv[i][k2]*(ph - pl);
        }
        ys[t*ROWS + i] = g_xT[(b*NN + n0 + i)*TT + t] + srow[i]*mix;
    }
    __syncthreads();

    float acc1[ROWS], acc2[ROWS];
    #pragma unroll
    for (int i = 0; i < ROWS; i++) { acc1[i] = 0.f; acc2[i] = 0.f; }
    #pragma unroll 2
    for (int t = 0; t < TT; t++) {
        float u1 = g_U1[t*PP + p];
        float u2 = g_U2[t*PP + p];
        const float4* row = (const float4*)&ys[t*ROWS];
        float4 v0 = row[0], v1 = row[1], v2 = row[2];
        acc1[0] += v0.x*u1;  acc2[0] += v0.x*u2;
        acc1[1] += v0.y*u1;  acc2[1] += v0.y*u2;
        acc1[2] += v0.z*u1;  acc2[2] += v0.z*u2;
        acc1[3] += v0.w*u1;  acc2[3] += v0.w*u2;
        acc1[4] += v1.x*u1;  acc2[4] += v1.x*u2;
        acc1[5] += v1.y*u1;  acc2[5] += v1.y*u2;
        acc1[6] += v1.z*u1;  acc2[6] += v1.z*u2;
        acc1[7] += v1.w*u1;  acc2[7] += v1.w*u2;
        acc1[8] += v2.x*u1;  acc2[8] += v2.x*u2;
        acc1[9] += v2.y*u1;  acc2[9] += v2.y*u2;
        acc1[10] += v2.z*u1; acc2[10] += v2.z*u2;
        acc1[11] += v2.w*u1; acc2[11] += v2.w*u2;
    }
    for (int i = 0; i < nrows; i++) {
        int n = n0 + i;
        g_O1[(b*NN + n)*PP + p] = acc1[i];
        g_O2[(b*NN + n)*PP + p] = acc2[i];
    }
}

// ================= k_fin: out = O1 + g*A_hat@O2 + consts =================
__global__ void k_fin(const float* __restrict__ ggp, float* __restrict__ out) {
    int b = blockIdx.y;
    int n = blockIdx.x*32 + threadIdx.x;
    if (n >= NN) return;
    float gg = ggp[0];
    int cnt = g_csr_cnt[n];
    float rterm = gg * g_rA[n];
    for (int p = threadIdx.y; p < PP; p += 8) {
        float acc = 0;
        for (int k = 0; k < cnt; k++)
            acc += g_csr_val[n*NN + k] * g_O2[(b*NN + g_csr_col[n*NN + k])*PP + p];
        out[((size_t)b*PP + p)*NN + n] =
            g_O1[(b*NN + n)*PP + p] + gg*acc + g_constP[p] + rterm*g_cwP[p];
    }
}

// ---------------- launcher ----------------
extern "C" void kernel_launch(void* const* d_in, const int* in_sizes, int n_in,
                              void* d_out, int out_size) {
    const float* x    = (const float*)d_in[0];
    const float* We   = (const float*)d_in[1];
    const float* be   = (const float*)d_in[2];
    const float* W1   = (const float*)d_in[3];
    const float* W2   = (const float*)d_in[4];
    const float* gate = (const float*)d_in[5];
    const float* Apr  = (const float*)d_in[6];
    const float* Wg   = (const float*)d_in[7];
    const float* ggcn = (const float*)d_in[8];
    const float* Wh   = (const float*)d_in[9];
    const float* bh   = (const float*)d_in[10];
    float* out = (float*)d_out;

    k_stage1<<<S1_S, 256>>>(x, We, be, W1, W2, gate, Apr, Wg, Wh);
    k_stage2<<<S2_CP, 256>>>(Apr, We, Wh, bh);
    k_stage3<<<S3_SEL, 256>>>();
    k_off<<<dim3((TT + 127)/128, BB), 128>>>();
    k_out<<<dim3((NN + ROWS - 1)/ROWS, BB), PP>>>();
    k_fin<<<dim3((NN + 31)/32, BB), dim3(32, 8)>>>(ggcn, out);
}